// round 15
// baseline (speedup 1.0000x reference)
#include <cuda_runtime.h>
#include <cstdint>
#include <math.h>

// ---------------- problem constants ----------------
#define S_ROWS 2047          // N_PART - 1
#define SPAD   2048
#define DIM    256
#define HID    512
#define NB     16
#define NFREQ  8
#define NBLK   4
#define NHEAD  8
#define EMB_IN 35
#define CONDP  64            // padded cond width
#define AFF_OUT 49
#define POS_ELEMS (2048*3)
#define KVSPLIT 2

// gemm smem: As[2][64][36] + Bs[2][64][36] uint2 (+ 512 uint2 combine cache)
#define GEMM_SMEM ((2*64*36 + 2*64*36 + 512) * 8)
// flash smem: Ks[2][64][36] + Vs[2][64][36] uint2
#define FLASH_SMEM ((2*64*36 + 2*64*36) * 8)

// ---------------- scratch (static device memory; zero-initialized) --------
__device__ float g_cond[SPAD * CONDP];
__device__ float g_a[SPAD * HID];
__device__ float g_b[SPAD * HID];
__device__ float g_h[SPAD * DIM];
__device__ float g_q[SPAD * DIM];
__device__ float g_k[SPAD * DIM];
__device__ float g_v[SPAD * DIM];
__device__ float g_po[KVSPLIT][SPAD * DIM];
__device__ float2 g_pml[KVSPLIT][SPAD * NHEAD];
__device__ float g_params[SPAD * AFF_OUT];
__device__ float g_ld[S_ROWS];

// ---------------- helpers ---------------------------------------------------
__device__ __forceinline__ uint32_t f2tf32(float f) {
    uint32_t u;
    asm("cvt.rna.tf32.f32 %0, %1;" : "=r"(u) : "f"(f));
    return u;
}

__device__ __forceinline__ uint2 split_tf32(float f) {
    uint32_t hi = f2tf32(f);
    uint32_t lo = f2tf32(f - __uint_as_float(hi));
    return make_uint2(hi, lo);
}

__device__ __forceinline__ void mma_tf32(float c[4], const uint32_t a[4],
                                         const uint32_t b[2]) {
    asm volatile(
        "mma.sync.aligned.m16n8k8.row.col.f32.tf32.tf32.f32 "
        "{%0,%1,%2,%3}, {%4,%5,%6,%7}, {%8,%9}, {%0,%1,%2,%3};"
        : "+f"(c[0]), "+f"(c[1]), "+f"(c[2]), "+f"(c[3])
        : "r"(a[0]), "r"(a[1]), "r"(a[2]), "r"(a[3]), "r"(b[0]), "r"(b[1]));
}

__device__ __forceinline__ void mma3(float c[4], const uint32_t aH[4],
                                     const uint32_t aL[4], const uint32_t bH[2],
                                     const uint32_t bL[2]) {
    mma_tf32(c, aL, bH);
    mma_tf32(c, aH, bL);
    mma_tf32(c, aH, bH);
}

__device__ __forceinline__ void pdl_wait() {
    cudaGridDependencySynchronize();
}
__device__ __forceinline__ void pdl_trigger() {
    cudaTriggerProgrammaticLaunchCompletion();
}

// ---------------- circular features (padded cond) ----------------------------
__global__ void embed_kernel(const float* __restrict__ pos,
                             const float* __restrict__ scale,
                             const float* __restrict__ press,
                             const float* __restrict__ temp,
                             float* __restrict__ cond) {
    // reads only harness inputs -> no pdl_wait needed
    int s = blockIdx.x * blockDim.x + threadIdx.x;
    if (s >= SPAD) return;
    float* c = cond + s * CONDP;
    if (s >= S_ROWS) {
        #pragma unroll
        for (int i = 0; i < CONDP; i++) c[i] = 0.f;
        return;
    }
    const float TWO_PI = 6.28318530717958647692f;
    float xs[2];
    xs[0] = pos[(s + 1) * 3 + 0];
    xs[1] = pos[(s + 1) * 3 + 1];
    #pragma unroll
    for (int cc = 0; cc < 2; cc++) {
        float x = xs[cc];
        #pragma unroll
        for (int f = 1; f <= NFREQ; f++) {
            float sn, cs;
            sincosf(TWO_PI * (float)f * x, &sn, &cs);
            c[cc * 16 + (f - 1)]     = cs;
            c[cc * 16 + 8 + (f - 1)] = sn;
        }
    }
    c[32] = *scale;
    c[33] = *temp;
    c[34] = *press;
    #pragma unroll
    for (int i = EMB_IN; i < CONDP; i++) c[i] = 0.f;
}

// ---------------- GEMM: 64x64 tile, double-buffered, prefetch, PDL -----------
#define GAS(b,r,c) sm[((b)*64 + (r))*36 + (c)]
#define GBS(b,r,c) sm[4608 + ((b)*64 + (r))*36 + (c)]
#define CE_OFF 9216

template <bool COMB>
__device__ __forceinline__
float4 loadA4(const float* __restrict__ A, int lda,
              const float* __restrict__ po1,
              const float2* __restrict__ ce,
              int m0, int row, int col) {
    if (!COMB) {
        return *(const float4*)(A + (size_t)row * lda + col);
    } else {
        float2 w = ce[(row - m0) * NHEAD + (col >> 5)];
        float4 p = *(const float4*)(A + (size_t)row * lda + col);
        float4 q = *(const float4*)(po1 + (size_t)row * lda + col);
        return make_float4(p.x * w.x + q.x * w.y, p.y * w.x + q.y * w.y,
                           p.z * w.x + q.z * w.y, p.w * w.x + q.w * w.y);
    }
}

template <bool RELU, bool FULL, bool COMB>
__device__ __forceinline__
void gemm_core(const float* __restrict__ A, int lda,
               const float* __restrict__ W,
               const float* __restrict__ bias, const float* __restrict__ res,
               float* __restrict__ C, int Nstore, int Kreal, int Kp,
               const float* __restrict__ po1,
               const float2* __restrict__ pml0,
               const float2* __restrict__ pml1) {
    extern __shared__ uint2 sm[];

    const int tid  = threadIdx.x;
    const int lane = tid & 31;
    const int wid  = tid >> 5;
    const int warp_m = wid >> 2;
    const int warp_n = wid & 3;
    const int g   = lane >> 2;
    const int tig = lane & 3;

    const int m0 = blockIdx.y * 64;
    const int n0 = blockIdx.x * 64;

    float2* ce = (float2*)(sm + CE_OFF);

    int ldRow[2], ldCol[2];
    #pragma unroll
    for (int i = 0; i < 2; i++) {
        int f4 = i * 256 + tid;
        ldRow[i] = f4 >> 3;
        ldCol[i] = (f4 & 7) * 4;
    }
    const int stages = Kp >> 5;

    float av[2][4], bv[2][4];

    // ---- independent prologue: W (weights, never device-written) ----
    #pragma unroll
    for (int i = 0; i < 2; i++) {
        if (FULL) {
            float4 w4 = *(const float4*)(W + (size_t)(n0 + ldRow[i]) * Kreal + ldCol[i]);
            bv[i][0] = w4.x; bv[i][1] = w4.y; bv[i][2] = w4.z; bv[i][3] = w4.w;
        } else {
            int n = n0 + ldRow[i];
            #pragma unroll
            for (int j = 0; j < 4; j++) {
                int kk = ldCol[i] + j;
                bv[i][j] = (n < Nstore && kk < Kreal)
                         ? W[(size_t)n * Kreal + kk] : 0.f;
            }
        }
    }

    // ---- wait for predecessor before touching its outputs ----
    pdl_wait();

    if (COMB) {
        for (int i = tid; i < 64 * NHEAD; i += 256) {
            int row = m0 + (i >> 3);
            int head = i & 7;
            float2 a = pml0[row * NHEAD + head];
            float2 b = pml1[row * NHEAD + head];
            float m = fmaxf(a.x, b.x);
            float e0 = __expf(a.x - m);
            float e1 = __expf(b.x - m);
            float den = a.y * e0 + b.y * e1;
            float inv = (den > 0.f) ? 1.f / den : 0.f;
            ce[i] = make_float2(e0 * inv, e1 * inv);
        }
        __syncthreads();
    }

    {
        #pragma unroll
        for (int i = 0; i < 2; i++) {
            float4 a4 = loadA4<COMB>(A, lda, po1, ce, m0, m0 + ldRow[i], ldCol[i]);
            av[i][0] = a4.x; av[i][1] = a4.y; av[i][2] = a4.z; av[i][3] = a4.w;
        }
        #pragma unroll
        for (int i = 0; i < 2; i++)
            #pragma unroll
            for (int j = 0; j < 4; j++) {
                GAS(0, ldRow[i], ldCol[i] + j) = split_tf32(av[i][j]);
                GBS(0, ldRow[i], ldCol[i] + j) = split_tf32(bv[i][j]);
            }
    }
    __syncthreads();

    float acc[2][2][4];
    #pragma unroll
    for (int mt = 0; mt < 2; mt++)
        #pragma unroll
        for (int nt = 0; nt < 2; nt++)
            #pragma unroll
            for (int i = 0; i < 4; i++) acc[mt][nt][i] = 0.f;

    for (int s = 0; s < stages; s++) {
        const int cur = s & 1;

        if (s + 1 < stages) {
            const int k0 = (s + 1) * 32;
            #pragma unroll
            for (int i = 0; i < 2; i++) {
                float4 a4 = loadA4<COMB>(A, lda, po1, ce, m0,
                                         m0 + ldRow[i], k0 + ldCol[i]);
                av[i][0] = a4.x; av[i][1] = a4.y; av[i][2] = a4.z; av[i][3] = a4.w;
                if (FULL) {
                    float4 w4 = *(const float4*)(W + (size_t)(n0 + ldRow[i]) * Kreal + k0 + ldCol[i]);
                    bv[i][0] = w4.x; bv[i][1] = w4.y; bv[i][2] = w4.z; bv[i][3] = w4.w;
                } else {
                    int n = n0 + ldRow[i];
                    #pragma unroll
                    for (int j = 0; j < 4; j++) {
                        int kk = k0 + ldCol[i] + j;
                        bv[i][j] = (n < Nstore && kk < Kreal)
                                 ? W[(size_t)n * Kreal + kk] : 0.f;
                    }
                }
            }
        }

        #pragma unroll
        for (int k8 = 0; k8 < 4; k8++) {
            const int kk = k8 * 8;
            uint32_t aH[2][4], aL[2][4];
            #pragma unroll
            for (int mt = 0; mt < 2; mt++) {
                const int r = warp_m * 32 + mt * 16 + g;
                uint2 p0 = GAS(cur, r,     kk + tig);
                uint2 p1 = GAS(cur, r + 8, kk + tig);
                uint2 p2 = GAS(cur, r,     kk + tig + 4);
                uint2 p3 = GAS(cur, r + 8, kk + tig + 4);
                aH[mt][0] = p0.x; aH[mt][1] = p1.x; aH[mt][2] = p2.x; aH[mt][3] = p3.x;
                aL[mt][0] = p0.y; aL[mt][1] = p1.y; aL[mt][2] = p2.y; aL[mt][3] = p3.y;
            }
            uint32_t bH[2][2], bL[2][2];
            #pragma unroll
            for (int nt = 0; nt < 2; nt++) {
                int ci = warp_n * 16 + nt * 8 + g;
                uint2 q0 = GBS(cur, ci, kk + tig);
                uint2 q1 = GBS(cur, ci, kk + tig + 4);
                bH[nt][0] = q0.x; bH[nt][1] = q1.x;
                bL[nt][0] = q0.y; bL[nt][1] = q1.y;
            }
            #pragma unroll
            for (int mt = 0; mt < 2; mt++)
                #pragma unroll
                for (int nt = 0; nt < 2; nt++)
                    mma3(acc[mt][nt], aH[mt], aL[mt], bH[nt], bL[nt]);
        }

        if (s + 1 < stages) {
            const int nb = (s + 1) & 1;
            #pragma unroll
            for (int i = 0; i < 2; i++)
                #pragma unroll
                for (int j = 0; j < 4; j++) {
                    GAS(nb, ldRow[i], ldCol[i] + j) = split_tf32(av[i][j]);
                    GBS(nb, ldRow[i], ldCol[i] + j) = split_tf32(bv[i][j]);
                }
        }
        __syncthreads();
    }

    pdl_trigger();   // all global input reads done; successor may launch

    #pragma unroll
    for (int mt = 0; mt < 2; mt++) {
        #pragma unroll
        for (int nt = 0; nt < 2; nt++) {
            int r0 = m0 + warp_m * 32 + mt * 16 + g;
            int cb = n0 + warp_n * 16 + nt * 8 + tig * 2;
            #pragma unroll
            for (int half = 0; half < 2; half++) {
                int r = r0 + half * 8;
                if (r >= S_ROWS) continue;
                #pragma unroll
                for (int j = 0; j < 2; j++) {
                    int n = cb + j;
                    if (n >= Nstore) continue;
                    float v = acc[mt][nt][half * 2 + j];
                    if (bias) v += bias[n];
                    if (res)  v += res[(size_t)r * Nstore + n];
                    if (RELU) v = fmaxf(v, 0.f);
                    C[(size_t)r * Nstore + n] = v;
                }
            }
        }
    }
}

template <bool RELU, bool FULL>
__global__ __launch_bounds__(256)
void gemm_v9_kernel(const float* __restrict__ A, int lda,
                    const float* __restrict__ W,
                    const float* __restrict__ bias, const float* __restrict__ res,
                    float* __restrict__ C, int Nstore, int Kreal, int Kp) {
    gemm_core<RELU, FULL, false>(A, lda, W, bias, res, C, Nstore, Kreal, Kp,
                                 nullptr, nullptr, nullptr);
}

__global__ __launch_bounds__(256)
void gemm_wo_kernel(const float* __restrict__ W,
                    const float* __restrict__ bias, const float* __restrict__ res,
                    float* __restrict__ C) {
    gemm_core<false, true, true>(g_po[0], DIM, W, bias, res, C, DIM, DIM, DIM,
                                 g_po[1], g_pml[0], g_pml[1]);
}

__global__ __launch_bounds__(256)
void gemm_qkv_kernel(const float* __restrict__ h,
                     const float* __restrict__ Wq, const float* __restrict__ Wk,
                     const float* __restrict__ Wv, const float* __restrict__ bk,
                     float* __restrict__ q, float* __restrict__ k,
                     float* __restrict__ v) {
    int z = blockIdx.z;
    const float* W = (z == 0) ? Wq : (z == 1) ? Wk : Wv;
    const float* bias = (z == 1) ? bk : nullptr;
    float* C = (z == 0) ? q : (z == 1) ? k : v;
    gemm_core<false, true, false>(h, DIM, W, bias, nullptr, C, DIM, DIM, DIM,
                                  nullptr, nullptr, nullptr);
}

// ---------------- flash attention: 128 q-rows / block, kv-split, PDL --------
#define FKS(b,r,c) sm[((b)*64 + (r))*36 + (c)]
#define FVS(b,r,c) sm[4608 + ((b)*64 + (r))*36 + (c)]

__global__ __launch_bounds__(256)
void flash_mma_kernel(const float* __restrict__ q,
                      const float* __restrict__ k,
                      const float* __restrict__ v) {
    extern __shared__ uint2 sm[];

    const int S = S_ROWS, D = DIM;
    const int head = blockIdx.y;
    const int z = blockIdx.z;
    const int s0 = blockIdx.x * 128;
    const int tid = threadIdx.x;
    const int lane = tid & 31;
    const int wid = tid >> 5;
    const int g = lane >> 2;
    const int tig = lane & 3;
    const float scl = 0.17677669529663688f;
    const int TPB = 32 / KVSPLIT;
    const int tbase = z * TPB;

    float4 kr[2], vr[2];
    int ldR[2], ldC[2];
    #pragma unroll
    for (int i = 0; i < 2; i++) {
        int cc = i * 256 + tid;
        ldR[i] = cc >> 3;
        ldC[i] = (cc & 7) * 4;
    }

    pdl_wait();   // q/k/v come from the qkv projection

    uint32_t aQH[4][4], aQL[4][4];
    {
        const int ra = s0 + wid * 16 + g;
        const int rb = ra + 8;
        #pragma unroll
        for (int k8 = 0; k8 < 4; k8++) {
            const int c0 = head * 32 + k8 * 8 + tig;
            uint2 p0 = split_tf32(q[(size_t)ra * D + c0] * scl);
            uint2 p1 = split_tf32(q[(size_t)rb * D + c0] * scl);
            uint2 p2 = split_tf32(q[(size_t)ra * D + c0 + 4] * scl);
            uint2 p3 = split_tf32(q[(size_t)rb * D + c0 + 4] * scl);
            aQH[k8][0] = p0.x; aQH[k8][1] = p1.x; aQH[k8][2] = p2.x; aQH[k8][3] = p3.x;
            aQL[k8][0] = p0.y; aQL[k8][1] = p1.y; aQL[k8][2] = p2.y; aQL[k8][3] = p3.y;
        }
    }

    #pragma unroll
    for (int i = 0; i < 2; i++) {
        size_t off = (size_t)(tbase * 64 + ldR[i]) * D + head * 32 + ldC[i];
        kr[i] = *(const float4*)&k[off];
        vr[i] = *(const float4*)&v[off];
    }
    #pragma unroll
    for (int i = 0; i < 2; i++) {
        FKS(0, ldR[i], ldC[i] + 0) = split_tf32(kr[i].x);
        FKS(0, ldR[i], ldC[i] + 1) = split_tf32(kr[i].y);
        FKS(0, ldR[i], ldC[i] + 2) = split_tf32(kr[i].z);
        FKS(0, ldR[i], ldC[i] + 3) = split_tf32(kr[i].w);
        FVS(0, ldR[i], ldC[i] + 0) = split_tf32(vr[i].x);
        FVS(0, ldR[i], ldC[i] + 1) = split_tf32(vr[i].y);
        FVS(0, ldR[i], ldC[i] + 2) = split_tf32(vr[i].z);
        FVS(0, ldR[i], ldC[i] + 3) = split_tf32(vr[i].w);
    }
    __syncthreads();

    float co[4][4];
    #pragma unroll
    for (int nt = 0; nt < 4; nt++)
        #pragma unroll
        for (int i = 0; i < 4; i++) co[nt][i] = 0.f;
    float m_a = -INFINITY, m_b = -INFINITY, l_a = 0.f, l_b = 0.f;

    for (int j = 0; j < TPB; j++) {
        const int cur = j & 1;
        const int t0 = (tbase + j) * 64;

        if (j + 1 < TPB) {
            const int t1 = t0 + 64;
            #pragma unroll
            for (int i = 0; i < 2; i++) {
                size_t off = (size_t)(t1 + ldR[i]) * D + head * 32 + ldC[i];
                kr[i] = *(const float4*)&k[off];
                vr[i] = *(const float4*)&v[off];
            }
        }

        float cs[8][4];
        #pragma unroll
        for (int nt = 0; nt < 8; nt++)
            #pragma unroll
            for (int i = 0; i < 4; i++) cs[nt][i] = 0.f;

        #pragma unroll
        for (int k8 = 0; k8 < 4; k8++) {
            const int kk = k8 * 8;
            #pragma unroll
            for (int nt = 0; nt < 8; nt++) {
                int ci = nt * 8 + g;
                uint2 q0 = FKS(cur, ci, kk + tig);
                uint2 q1 = FKS(cur, ci, kk + tig + 4);
                uint32_t bH[2] = {q0.x, q1.x};
                uint32_t bL[2] = {q0.y, q1.y};
                mma3(cs[nt], aQH[k8], aQL[k8], bH, bL);
            }
        }

        float mx_a = m_a, mx_b = m_b;
        #pragma unroll
        for (int nt = 0; nt < 8; nt++) {
            int col0 = t0 + nt * 8 + 2 * tig;
            if (col0 >= S)     { cs[nt][0] = -INFINITY; cs[nt][2] = -INFINITY; }
            if (col0 + 1 >= S) { cs[nt][1] = -INFINITY; cs[nt][3] = -INFINITY; }
            mx_a = fmaxf(mx_a, fmaxf(cs[nt][0], cs[nt][1]));
            mx_b = fmaxf(mx_b, fmaxf(cs[nt][2], cs[nt][3]));
        }
        mx_a = fmaxf(mx_a, __shfl_xor_sync(0xffffffffu, mx_a, 1));
        mx_a = fmaxf(mx_a, __shfl_xor_sync(0xffffffffu, mx_a, 2));
        mx_b = fmaxf(mx_b, __shfl_xor_sync(0xffffffffu, mx_b, 1));
        mx_b = fmaxf(mx_b, __shfl_xor_sync(0xffffffffu, mx_b, 2));
        float corr_a = __expf(m_a - mx_a);
        float corr_b = __expf(m_b - mx_b);
        m_a = mx_a; m_b = mx_b;

        float la = 0.f, lb = 0.f;
        #pragma unroll
        for (int nt = 0; nt < 8; nt++) {
            cs[nt][0] = __expf(cs[nt][0] - m_a);
            cs[nt][1] = __expf(cs[nt][1] - m_a);
            cs[nt][2] = __expf(cs[nt][2] - m_b);
            cs[nt][3] = __expf(cs[nt][3] - m_b);
            la += cs[nt][0] + cs[nt][1];
            lb += cs[nt][2] + cs[nt][3];
        }
        la += __shfl_xor_sync(0xffffffffu, la, 1);
        la += __shfl_xor_sync(0xffffffffu, la, 2);
        lb += __shfl_xor_sync(0xffffffffu, lb, 1);
        lb += __shfl_xor_sync(0xffffffffu, lb, 2);
        l_a = l_a * corr_a + la;
        l_b = l_b * corr_b + lb;

        #pragma unroll
        for (int nt = 0; nt < 4; nt++) {
            co[nt][0] *= corr_a; co[nt][1] *= corr_a;
            co[nt][2] *= corr_b; co[nt][3] *= corr_b;
        }

        // PV: permute score C-frags -> A-frags via quad shuffles
        {
            const int s1 = (lane & ~3) | (tig >> 1);
            const int s2 = s1 + 2;
            const bool odd = (tig & 1) != 0;
            #pragma unroll
            for (int k8v = 0; k8v < 8; k8v++) {
                float q00 = __shfl_sync(0xffffffffu, cs[k8v][0], s1);
                float q01 = __shfl_sync(0xffffffffu, cs[k8v][1], s1);
                float q02 = __shfl_sync(0xffffffffu, cs[k8v][2], s1);
                float q03 = __shfl_sync(0xffffffffu, cs[k8v][3], s1);
                float r00 = __shfl_sync(0xffffffffu, cs[k8v][0], s2);
                float r01 = __shfl_sync(0xffffffffu, cs[k8v][1], s2);
                float r02 = __shfl_sync(0xffffffffu, cs[k8v][2], s2);
                float r03 = __shfl_sync(0xffffffffu, cs[k8v][3], s2);
                float a0 = odd ? q01 : q00;
                float a1 = odd ? q03 : q02;
                float a2 = odd ? r01 : r00;
                float a3 = odd ? r03 : r02;
                uint2 h0 = split_tf32(a0), h1 = split_tf32(a1);
                uint2 h2 = split_tf32(a2), h3 = split_tf32(a3);
                uint32_t aH[4] = {h0.x, h1.x, h2.x, h3.x};
                uint32_t aL[4] = {h0.y, h1.y, h2.y, h3.y};
                const int kkv = k8v * 8;
                #pragma unroll
                for (int nt = 0; nt < 4; nt++) {
                    uint2 q0 = FVS(cur, kkv + tig,     nt * 8 + g);
                    uint2 q1 = FVS(cur, kkv + tig + 4, nt * 8 + g);
                    uint32_t bH[2] = {q0.x, q1.x};
                    uint32_t bL[2] = {q0.y, q1.y};
                    mma3(co[nt], aH, aL, bH, bL);
                }
            }
        }

        if (j + 1 < TPB) {
            const int nb = (j + 1) & 1;
            #pragma unroll
            for (int i = 0; i < 2; i++) {
                FKS(nb, ldR[i], ldC[i] + 0) = split_tf32(kr[i].x);
                FKS(nb, ldR[i], ldC[i] + 1) = split_tf32(kr[i].y);
                FKS(nb, ldR[i], ldC[i] + 2) = split_tf32(kr[i].z);
                FKS(nb, ldR[i], ldC[i] + 3) = split_tf32(kr[i].w);
                FVS(nb, ldR[i], ldC[i] + 0) = split_tf32(vr[i].x);
                FVS(nb, ldR[i], ldC[i] + 1) = split_tf32(vr[i].y);
                FVS(nb, ldR[i], ldC[i] + 2) = split_tf32(vr[i].z);
                FVS(nb, ldR[i], ldC[i] + 3) = split_tf32(vr[i].w);
            }
            __syncthreads();
        }
    }

    pdl_trigger();

    float* po = g_po[z];
    int srow_a = s0 + wid * 16 + g;
    int srow_b = srow_a + 8;
    #pragma unroll
    for (int nt = 0; nt < 4; nt++) {
        int col = head * 32 + nt * 8 + 2 * tig;
        if (srow_a < S) {
            float2 w2 = make_float2(co[nt][0], co[nt][1]);
            *(float2*)&po[(size_t)srow_a * D + col] = w2;
        }
        if (srow_b < S) {
            float2 w2 = make_float2(co[nt][2], co[nt][3]);
            *(float2*)&po[(size_t)srow_b * D + col] = w2;
        }
    }
    if (tig == 0) {
        if (srow_a < S) g_pml[z][(size_t)srow_a * NHEAD + head] = make_float2(m_a, l_a);
        if (srow_b < S) g_pml[z][(size_t)srow_b * NHEAD + head] = make_float2(m_b, l_b);
    }
}

// ---------------- RQS spline (+ fused pos copy) ------------------------------
__device__ __forceinline__ float softplusf(float x) {
    return (x > 20.f) ? x : log1pf(expf(x));
}

__global__ void spline_kernel(const float* __restrict__ pos,
                              const float* __restrict__ params,
                              float* __restrict__ out,
                              float* __restrict__ ld) {
    pdl_wait();   // params from affine head
    int t = blockIdx.x * blockDim.x + threadIdx.x;
    if (t >= SPAD) return;

    out[t * 3 + 0] = pos[t * 3 + 0];
    out[t * 3 + 1] = pos[t * 3 + 1];
    out[t * 3 + 2] = pos[t * 3 + 2];

    if (t < 1) return;
    int s = t - 1;
    const float* p = params + s * AFF_OUT;
    const float MINB = 1e-4f;
    const float MINS = 1e-4f;

    float x = pos[t * 3 + 2];
    bool inside = (x >= 0.f) && (x <= 1.f);
    float xc = fminf(fmaxf(x, 0.f), 1.f);

    float ew[NB], eh[NB];
    float mw = -INFINITY, mh = -INFINITY;
    #pragma unroll
    for (int i = 0; i < NB; i++) { mw = fmaxf(mw, p[i]); mh = fmaxf(mh, p[NB + i]); }
    float sw = 0.f, sh = 0.f;
    #pragma unroll
    for (int i = 0; i < NB; i++) {
        ew[i] = expf(p[i] - mw);        sw += ew[i];
        eh[i] = expf(p[NB + i] - mh);   sh += eh[i];
    }
    float fac = 1.f - NB * MINB;
    float isw = fac / sw, ish = fac / sh;

    float off = logf(expm1f(1.f - MINS));
    float d[NB + 1];
    #pragma unroll
    for (int i = 0; i < NB; i++) d[i] = softplusf(p[2 * NB + i] + off) + MINS;
    d[NB] = d[0];

    float xp[NB + 1], yp[NB + 1];
    xp[0] = 0.f; yp[0] = 0.f;
    #pragma unroll
    for (int i = 0; i < NB; i++) {
        xp[i + 1] = xp[i] + (ew[i] * isw + MINB);
        yp[i + 1] = yp[i] + (eh[i] * ish + MINB);
    }

    int cnt = 0;
    #pragma unroll
    for (int i = 0; i < NB + 1; i++) cnt += (xc >= xp[i]) ? 1 : 0;
    int kb = cnt - 1;
    if (kb < 0) kb = 0;
    if (kb > NB - 1) kb = NB - 1;

    float xk = xp[kb], xk1 = xp[kb + 1];
    float yk = yp[kb], yk1 = yp[kb + 1];
    float dk = d[kb],  dk1 = d[kb + 1];
    float w = xk1 - xk;
    float h = yk1 - yk;
    float sl = h / w;
    float z = (xc - xk) / w;
    float z1 = 1.f - z;
    float den = sl + (dk1 + dk - 2.f * sl) * z * z1;
    float y = yk + h * (sl * z * z + dk * z * z1) / den;
    float logdet = 2.f * logf(sl)
                 + logf(dk1 * z * z + 2.f * sl * z * z1 + dk * z1 * z1)
                 - 2.f * logf(den);

    out[t * 3 + 2] = inside ? y : x;
    ld[s] = inside ? logdet : 0.f;
}

// ---------------- deterministic logdet reduction ----------------------------
__global__ void reduce_kernel(const float* __restrict__ ld,
                              float* __restrict__ out, int out_size) {
    pdl_wait();
    __shared__ float sh[256];
    float s = 0.f;
    for (int i = threadIdx.x; i < S_ROWS; i += 256) s += ld[i];
    sh[threadIdx.x] = s;
    __syncthreads();
    for (int st = 128; st > 0; st >>= 1) {
        if (threadIdx.x < st) sh[threadIdx.x] += sh[threadIdx.x + st];
        __syncthreads();
    }
    if (threadIdx.x == 0 && out_size > POS_ELEMS) out[POS_ELEMS] = sh[0];
}

// ---------------- host orchestration ---------------------------------------
template <typename T>
static void* sym_addr_raw(T& sym) {
    void* p = nullptr;
    cudaGetSymbolAddress(&p, sym);
    return p;
}

static cudaLaunchConfig_t pdl_cfg(dim3 g, dim3 b, size_t smem) {
    static cudaLaunchAttribute attr[1];
    attr[0].id = cudaLaunchAttributeProgrammaticStreamSerialization;
    attr[0].val.programmaticStreamSerializationAllowed = 1;
    cudaLaunchConfig_t c = {};
    c.gridDim = g;
    c.blockDim = b;
    c.dynamicSmemBytes = smem;
    c.stream = 0;
    c.attrs = attr;
    c.numAttrs = 1;
    return c;
}

static void gemm(const float* A, int lda, const float* W, const float* bias,
                 const float* res, float* C, int Nstore, int Npad,
                 int Kreal, int Kp, bool relu) {
    dim3 grid(Npad / 64, SPAD / 64);
    bool full = (Nstore % 64 == 0) && (Kreal == Kp);
    cudaLaunchConfig_t c = pdl_cfg(grid, dim3(256), GEMM_SMEM);
    if (full) {
        if (relu)
            cudaLaunchKernelEx(&c, gemm_v9_kernel<true , true >, A, lda, W, bias, res, C, Nstore, Kreal, Kp);
        else
            cudaLaunchKernelEx(&c, gemm_v9_kernel<false, true >, A, lda, W, bias, res, C, Nstore, Kreal, Kp);
    } else {
        if (relu)
            cudaLaunchKernelEx(&c, gemm_v9_kernel<true , false>, A, lda, W, bias, res, C, Nstore, Kreal, Kp);
        else
            cudaLaunchKernelEx(&c, gemm_v9_kernel<false, false>, A, lda, W, bias, res, C, Nstore, Kreal, Kp);
    }
}

extern "C" void kernel_launch(void* const* d_in, const int* in_sizes, int n_in,
                              void* d_out, int out_size) {
    const float* pos   = (const float*)d_in[0];
    const float* scale = (const float*)d_in[1];
    const float* press = (const float*)d_in[2];
    const float* temp  = (const float*)d_in[3];
    const float* e_w0 = (const float*)d_in[4];
    const float* e_b0 = (const float*)d_in[5];
    const float* e_w1 = (const float*)d_in[6];
    const float* e_b1 = (const float*)d_in[7];
    const float* e_w2 = (const float*)d_in[8];
    const float* e_b2 = (const float*)d_in[9];
    const float* Wq   = (const float*)d_in[10];
    const float* Wk   = (const float*)d_in[11];
    const float* bk   = (const float*)d_in[12];
    const float* Wv   = (const float*)d_in[13];
    const float* Wo   = (const float*)d_in[14];
    const float* bo   = (const float*)d_in[15];
    const float* mw0  = (const float*)d_in[16];
    const float* mb0  = (const float*)d_in[17];
    const float* mw1  = (const float*)d_in[18];
    const float* mb1  = (const float*)d_in[19];
    const float* mw2  = (const float*)d_in[20];
    const float* mb2  = (const float*)d_in[21];
    const float* a_w0 = (const float*)d_in[22];
    const float* a_b0 = (const float*)d_in[23];
    const float* a_w1 = (const float*)d_in[24];
    const float* a_b1 = (const float*)d_in[25];
    const float* a_w2 = (const float*)d_in[26];
    const float* a_b2 = (const float*)d_in[27];

    float* cond   = (float*)sym_addr_raw(g_cond);
    float* bufA   = (float*)sym_addr_raw(g_a);
    float* bufB   = (float*)sym_addr_raw(g_b);
    float* h      = (float*)sym_addr_raw(g_h);
    float* q      = (float*)sym_addr_raw(g_q);
    float* k      = (float*)sym_addr_raw(g_k);
    float* v      = (float*)sym_addr_raw(g_v);
    float* params = (float*)sym_addr_raw(g_params);
    float* ld     = (float*)sym_addr_raw(g_ld);
    float* out    = (float*)d_out;

    cudaFuncSetAttribute(gemm_v9_kernel<true , true >,
                         cudaFuncAttributeMaxDynamicSharedMemorySize, GEMM_SMEM);
    cudaFuncSetAttribute(gemm_v9_kernel<false, true >,
                         cudaFuncAttributeMaxDynamicSharedMemorySize, GEMM_SMEM);
    cudaFuncSetAttribute(gemm_v9_kernel<true , false>,
                         cudaFuncAttributeMaxDynamicSharedMemorySize, GEMM_SMEM);
    cudaFuncSetAttribute(gemm_v9_kernel<false, false>,
                         cudaFuncAttributeMaxDynamicSharedMemorySize, GEMM_SMEM);
    cudaFuncSetAttribute(gemm_wo_kernel,
                         cudaFuncAttributeMaxDynamicSharedMemorySize, GEMM_SMEM);
    cudaFuncSetAttribute(gemm_qkv_kernel,
                         cudaFuncAttributeMaxDynamicSharedMemorySize, GEMM_SMEM);
    cudaFuncSetAttribute(flash_mma_kernel,
                         cudaFuncAttributeMaxDynamicSharedMemorySize, FLASH_SMEM);

    {
        cudaLaunchConfig_t c = pdl_cfg(dim3(SPAD / 256), dim3(256), 0);
        cudaLaunchKernelEx(&c, embed_kernel, pos, scale, press, temp, cond);
    }

    // embedding MLP: 35 -> 512 -> 512 -> 256
    gemm(cond, CONDP, e_w0, e_b0, nullptr, bufA, HID, HID, EMB_IN, CONDP, true);
    gemm(bufA, HID,   e_w1, e_b1, nullptr, bufB, HID, HID, HID, HID, true);
    gemm(bufB, HID,   e_w2, e_b2, nullptr, h,    DIM, DIM, HID, HID, false);

    for (int i = 0; i < NBLK; i++) {
        const float* Wqi = Wq + (size_t)i * DIM * DIM;
        const float* Wki = Wk + (size_t)i * DIM * DIM;
        const float* bki = bk + (size_t)i * DIM;
        const float* Wvi = Wv + (size_t)i * DIM * DIM;
        const float* Woi = Wo + (size_t)i * DIM * DIM;
        const float* boi = bo + (size_t)i * DIM;
        const float* mw0i = mw0 + (size_t)i * HID * DIM;
        const float* mb0i = mb0 + (size_t)i * HID;
        const float* mw1i = mw1 + (size_t)i * HID * HID;
        const float* mb1i = mb1 + (size_t)i * HID;
        const float* mw2i = mw2 + (size_t)i * DIM * HID;
        const float* mb2i = mb2 + (size_t)i * DIM;

        {
            cudaLaunchConfig_t c = pdl_cfg(dim3(DIM / 64, SPAD / 64, 3),
                                           dim3(256), GEMM_SMEM);
            cudaLaunchKernelEx(&c, gemm_qkv_kernel, (const float*)h, Wqi, Wki,
                               Wvi, bki, q, k, v);
        }
        {
            cudaLaunchConfig_t c = pdl_cfg(dim3(SPAD / 128, NHEAD, KVSPLIT),
                                           dim3(256), FLASH_SMEM);
            cudaLaunchKernelEx(&c, flash_mma_kernel, (const float*)q,
                               (const float*)k, (const float*)v);
        }
        {
            cudaLaunchConfig_t c = pdl_cfg(dim3(DIM / 64, SPAD / 64),
                                           dim3(256), GEMM_SMEM);
            cudaLaunchKernelEx(&c, gemm_wo_kernel, Woi, boi,
                               (const float*)h, h);
        }

        gemm(h,    DIM, mw0i, mb0i, nullptr, bufA, HID, HID, DIM, DIM, true);
        gemm(bufA, HID, mw1i, mb1i, nullptr, bufB, HID, HID, HID, HID, true);
        gemm(bufB, HID, mw2i, mb2i, h,       h,    DIM, DIM, HID, HID, false);
    }

    // affine head: 256 -> 512 -> 512 -> 49
    gemm(h,    DIM, a_w0, a_b0, nullptr, bufA,   HID,     HID, DIM, DIM, true);
    gemm(bufA, HID, a_w1, a_b1, nullptr, bufB,   HID,     HID, HID, HID, true);
    gemm(bufB, HID, a_w2, a_b2, nullptr, params, AFF_OUT, 64,  HID, HID, false);

    {
        cudaLaunchConfig_t c = pdl_cfg(dim3(SPAD / 256), dim3(256), 0);
        cudaLaunchKernelEx(&c, spline_kernel, pos, (const float*)params,
                           out, ld);
    }
    {
        cudaLaunchConfig_t c = pdl_cfg(dim3(1), dim3(256), 0);
        cudaLaunchKernelEx(&c, reduce_kernel, (const float*)ld, out, out_size);
    }
}

// round 16
// speedup vs baseline: 1.0566x; 1.0566x over previous
#include <cuda_runtime.h>
#include <cstdint>
#include <math.h>

// ---------------- problem constants ----------------
#define S_ROWS 2047          // N_PART - 1
#define SPAD   2048
#define DIM    256
#define HID    512
#define NB     16
#define NFREQ  8
#define NBLK   4
#define NHEAD  8
#define EMB_IN 35
#define CONDP  64            // padded cond width
#define AFF_OUT 49
#define POS_ELEMS (2048*3)
#define KVSPLIT 2
#define SPLINE_BLOCKS (SPAD / 256)

// gemm smem: As[2][64][36] + Bs[2][64][36] uint2 (+ 512 uint2 combine cache)
#define GEMM_SMEM ((2*64*36 + 2*64*36 + 512) * 8)
// flash smem: Ks[2][64][36] + Vs[2][64][36] uint2
#define FLASH_SMEM ((2*64*36 + 2*64*36) * 8)

// ---------------- scratch (static device memory; zero-initialized) --------
__device__ float g_cond[SPAD * CONDP];
__device__ float g_a[SPAD * HID];
__device__ float g_b[SPAD * HID];
__device__ float g_h[SPAD * DIM];
__device__ float g_q[SPAD * DIM];
__device__ float g_k[SPAD * DIM];
__device__ float g_v[SPAD * DIM];
__device__ float g_po[KVSPLIT][SPAD * DIM];
__device__ float2 g_pml[KVSPLIT][SPAD * NHEAD];
__device__ float g_params[SPAD * AFF_OUT];
__device__ float g_partial[SPLINE_BLOCKS];
__device__ int   g_arrive;           // zero-init; self-resetting

// ---------------- helpers ---------------------------------------------------
__device__ __forceinline__ uint32_t f2tf32(float f) {
    uint32_t u;
    asm("cvt.rna.tf32.f32 %0, %1;" : "=r"(u) : "f"(f));
    return u;
}

__device__ __forceinline__ uint2 split_tf32(float f) {
    uint32_t hi = f2tf32(f);
    uint32_t lo = f2tf32(f - __uint_as_float(hi));
    return make_uint2(hi, lo);
}

__device__ __forceinline__ void mma_tf32(float c[4], const uint32_t a[4],
                                         const uint32_t b[2]) {
    asm volatile(
        "mma.sync.aligned.m16n8k8.row.col.f32.tf32.tf32.f32 "
        "{%0,%1,%2,%3}, {%4,%5,%6,%7}, {%8,%9}, {%0,%1,%2,%3};"
        : "+f"(c[0]), "+f"(c[1]), "+f"(c[2]), "+f"(c[3])
        : "r"(a[0]), "r"(a[1]), "r"(a[2]), "r"(a[3]), "r"(b[0]), "r"(b[1]));
}

__device__ __forceinline__ void mma3(float c[4], const uint32_t aH[4],
                                     const uint32_t aL[4], const uint32_t bH[2],
                                     const uint32_t bL[2]) {
    mma_tf32(c, aL, bH);
    mma_tf32(c, aH, bL);
    mma_tf32(c, aH, bH);
}

// ---------------- circular features (padded cond) ----------------------------
__global__ void embed_kernel(const float* __restrict__ pos,
                             const float* __restrict__ scale,
                             const float* __restrict__ press,
                             const float* __restrict__ temp,
                             float* __restrict__ cond) {
    int s = blockIdx.x * blockDim.x + threadIdx.x;
    if (s >= SPAD) return;
    float* c = cond + s * CONDP;
    if (s >= S_ROWS) {
        #pragma unroll
        for (int i = 0; i < CONDP; i++) c[i] = 0.f;
        return;
    }
    const float TWO_PI = 6.28318530717958647692f;
    float xs[2];
    xs[0] = pos[(s + 1) * 3 + 0];
    xs[1] = pos[(s + 1) * 3 + 1];
    #pragma unroll
    for (int cc = 0; cc < 2; cc++) {
        float x = xs[cc];
        #pragma unroll
        for (int f = 1; f <= NFREQ; f++) {
            float sn, cs;
            sincosf(TWO_PI * (float)f * x, &sn, &cs);
            c[cc * 16 + (f - 1)]     = cs;
            c[cc * 16 + 8 + (f - 1)] = sn;
        }
    }
    c[32] = *scale;
    c[33] = *temp;
    c[34] = *press;
    #pragma unroll
    for (int i = EMB_IN; i < CONDP; i++) c[i] = 0.f;
}

// ---------------- GEMM: 64x64 tile, double-buffered, prefetch ----------------
#define GAS(b,r,c) sm[((b)*64 + (r))*36 + (c)]
#define GBS(b,r,c) sm[4608 + ((b)*64 + (r))*36 + (c)]
#define CE_OFF 9216

template <bool COMB>
__device__ __forceinline__
float4 loadA4(const float* __restrict__ A, int lda,
              const float* __restrict__ po1,
              const float2* __restrict__ ce,
              int m0, int row, int col) {
    if (!COMB) {
        return *(const float4*)(A + (size_t)row * lda + col);
    } else {
        float2 w = ce[(row - m0) * NHEAD + (col >> 5)];
        float4 p = *(const float4*)(A + (size_t)row * lda + col);
        float4 q = *(const float4*)(po1 + (size_t)row * lda + col);
        return make_float4(p.x * w.x + q.x * w.y, p.y * w.x + q.y * w.y,
                           p.z * w.x + q.z * w.y, p.w * w.x + q.w * w.y);
    }
}

template <bool RELU, bool FULL, bool COMB>
__device__ __forceinline__
void gemm_core(const float* __restrict__ A, int lda,
               const float* __restrict__ W,
               const float* __restrict__ bias, const float* __restrict__ res,
               float* __restrict__ C, int Nstore, int Kreal, int Kp,
               const float* __restrict__ po1,
               const float2* __restrict__ pml0,
               const float2* __restrict__ pml1) {
    extern __shared__ uint2 sm[];

    const int tid  = threadIdx.x;
    const int lane = tid & 31;
    const int wid  = tid >> 5;
    const int warp_m = wid >> 2;
    const int warp_n = wid & 3;
    const int g   = lane >> 2;
    const int tig = lane & 3;

    const int m0 = blockIdx.y * 64;
    const int n0 = blockIdx.x * 64;

    float2* ce = (float2*)(sm + CE_OFF);
    if (COMB) {
        for (int i = tid; i < 64 * NHEAD; i += 256) {
            int row = m0 + (i >> 3);
            int head = i & 7;
            float2 a = pml0[row * NHEAD + head];
            float2 b = pml1[row * NHEAD + head];
            float m = fmaxf(a.x, b.x);
            float e0 = __expf(a.x - m);
            float e1 = __expf(b.x - m);
            float den = a.y * e0 + b.y * e1;
            float inv = (den > 0.f) ? 1.f / den : 0.f;
            ce[i] = make_float2(e0 * inv, e1 * inv);
        }
        __syncthreads();
    }

    int ldRow[2], ldCol[2];
    #pragma unroll
    for (int i = 0; i < 2; i++) {
        int f4 = i * 256 + tid;
        ldRow[i] = f4 >> 3;
        ldCol[i] = (f4 & 7) * 4;
    }
    const int stages = Kp >> 5;

    float av[2][4], bv[2][4];

    {
        #pragma unroll
        for (int i = 0; i < 2; i++) {
            float4 a4 = loadA4<COMB>(A, lda, po1, ce, m0, m0 + ldRow[i], ldCol[i]);
            av[i][0] = a4.x; av[i][1] = a4.y; av[i][2] = a4.z; av[i][3] = a4.w;
            if (FULL) {
                float4 w4 = *(const float4*)(W + (size_t)(n0 + ldRow[i]) * Kreal + ldCol[i]);
                bv[i][0] = w4.x; bv[i][1] = w4.y; bv[i][2] = w4.z; bv[i][3] = w4.w;
            } else {
                int n = n0 + ldRow[i];
                #pragma unroll
                for (int j = 0; j < 4; j++) {
                    int kk = ldCol[i] + j;
                    bv[i][j] = (n < Nstore && kk < Kreal)
                             ? W[(size_t)n * Kreal + kk] : 0.f;
                }
            }
        }
        #pragma unroll
        for (int i = 0; i < 2; i++)
            #pragma unroll
            for (int j = 0; j < 4; j++) {
                GAS(0, ldRow[i], ldCol[i] + j) = split_tf32(av[i][j]);
                GBS(0, ldRow[i], ldCol[i] + j) = split_tf32(bv[i][j]);
            }
    }
    __syncthreads();

    float acc[2][2][4];
    #pragma unroll
    for (int mt = 0; mt < 2; mt++)
        #pragma unroll
        for (int nt = 0; nt < 2; nt++)
            #pragma unroll
            for (int i = 0; i < 4; i++) acc[mt][nt][i] = 0.f;

    for (int s = 0; s < stages; s++) {
        const int cur = s & 1;

        if (s + 1 < stages) {
            const int k0 = (s + 1) * 32;
            #pragma unroll
            for (int i = 0; i < 2; i++) {
                float4 a4 = loadA4<COMB>(A, lda, po1, ce, m0,
                                         m0 + ldRow[i], k0 + ldCol[i]);
                av[i][0] = a4.x; av[i][1] = a4.y; av[i][2] = a4.z; av[i][3] = a4.w;
                if (FULL) {
                    float4 w4 = *(const float4*)(W + (size_t)(n0 + ldRow[i]) * Kreal + k0 + ldCol[i]);
                    bv[i][0] = w4.x; bv[i][1] = w4.y; bv[i][2] = w4.z; bv[i][3] = w4.w;
                } else {
                    int n = n0 + ldRow[i];
                    #pragma unroll
                    for (int j = 0; j < 4; j++) {
                        int kk = k0 + ldCol[i] + j;
                        bv[i][j] = (n < Nstore && kk < Kreal)
                                 ? W[(size_t)n * Kreal + kk] : 0.f;
                    }
                }
            }
        }

        #pragma unroll
        for (int k8 = 0; k8 < 4; k8++) {
            const int kk = k8 * 8;
            uint32_t aH[2][4], aL[2][4];
            #pragma unroll
            for (int mt = 0; mt < 2; mt++) {
                const int r = warp_m * 32 + mt * 16 + g;
                uint2 p0 = GAS(cur, r,     kk + tig);
                uint2 p1 = GAS(cur, r + 8, kk + tig);
                uint2 p2 = GAS(cur, r,     kk + tig + 4);
                uint2 p3 = GAS(cur, r + 8, kk + tig + 4);
                aH[mt][0] = p0.x; aH[mt][1] = p1.x; aH[mt][2] = p2.x; aH[mt][3] = p3.x;
                aL[mt][0] = p0.y; aL[mt][1] = p1.y; aL[mt][2] = p2.y; aL[mt][3] = p3.y;
            }
            uint32_t bH[2][2], bL[2][2];
            #pragma unroll
            for (int nt = 0; nt < 2; nt++) {
                int ci = warp_n * 16 + nt * 8 + g;
                uint2 q0 = GBS(cur, ci, kk + tig);
                uint2 q1 = GBS(cur, ci, kk + tig + 4);
                bH[nt][0] = q0.x; bH[nt][1] = q1.x;
                bL[nt][0] = q0.y; bL[nt][1] = q1.y;
            }
            #pragma unroll
            for (int mt = 0; mt < 2; mt++)
                #pragma unroll
                for (int nt = 0; nt < 2; nt++)
                    mma3(acc[mt][nt], aH[mt], aL[mt], bH[nt], bL[nt]);
        }

        if (s + 1 < stages) {
            const int nb = (s + 1) & 1;
            #pragma unroll
            for (int i = 0; i < 2; i++)
                #pragma unroll
                for (int j = 0; j < 4; j++) {
                    GAS(nb, ldRow[i], ldCol[i] + j) = split_tf32(av[i][j]);
                    GBS(nb, ldRow[i], ldCol[i] + j) = split_tf32(bv[i][j]);
                }
        }
        __syncthreads();
    }

    #pragma unroll
    for (int mt = 0; mt < 2; mt++) {
        #pragma unroll
        for (int nt = 0; nt < 2; nt++) {
            int r0 = m0 + warp_m * 32 + mt * 16 + g;
            int cb = n0 + warp_n * 16 + nt * 8 + tig * 2;
            #pragma unroll
            for (int half = 0; half < 2; half++) {
                int r = r0 + half * 8;
                if (r >= S_ROWS) continue;
                #pragma unroll
                for (int j = 0; j < 2; j++) {
                    int n = cb + j;
                    if (n >= Nstore) continue;
                    float v = acc[mt][nt][half * 2 + j];
                    if (bias) v += bias[n];
                    if (res)  v += res[(size_t)r * Nstore + n];
                    if (RELU) v = fmaxf(v, 0.f);
                    C[(size_t)r * Nstore + n] = v;
                }
            }
        }
    }
}

template <bool RELU, bool FULL>
__global__ __launch_bounds__(256)
void gemm_v9_kernel(const float* __restrict__ A, int lda,
                    const float* __restrict__ W,
                    const float* __restrict__ bias, const float* __restrict__ res,
                    float* __restrict__ C, int Nstore, int Kreal, int Kp) {
    gemm_core<RELU, FULL, false>(A, lda, W, bias, res, C, Nstore, Kreal, Kp,
                                 nullptr, nullptr, nullptr);
}

// Wo projection with fused flash combine (smem-cached weights)
__global__ __launch_bounds__(256)
void gemm_wo_kernel(const float* __restrict__ W,
                    const float* __restrict__ bias, const float* __restrict__ res,
                    float* __restrict__ C) {
    gemm_core<false, true, true>(g_po[0], DIM, W, bias, res, C, DIM, DIM, DIM,
                                 g_po[1], g_pml[0], g_pml[1]);
}

// fused q/k/v projection via blockIdx.z
__global__ __launch_bounds__(256)
void gemm_qkv_kernel(const float* __restrict__ h,
                     const float* __restrict__ Wq, const float* __restrict__ Wk,
                     const float* __restrict__ Wv, const float* __restrict__ bk,
                     float* __restrict__ q, float* __restrict__ k,
                     float* __restrict__ v) {
    int z = blockIdx.z;
    const float* W = (z == 0) ? Wq : (z == 1) ? Wk : Wv;
    const float* bias = (z == 1) ? bk : nullptr;
    float* C = (z == 0) ? q : (z == 1) ? k : v;
    gemm_core<false, true, false>(h, DIM, W, bias, nullptr, C, DIM, DIM, DIM,
                                  nullptr, nullptr, nullptr);
}

// ---------------- flash attention: 128 q-rows / block, kv-split -------------
#define FKS(b,r,c) sm[((b)*64 + (r))*36 + (c)]
#define FVS(b,r,c) sm[4608 + ((b)*64 + (r))*36 + (c)]

__global__ __launch_bounds__(256)
void flash_mma_kernel(const float* __restrict__ q,
                      const float* __restrict__ k,
                      const float* __restrict__ v) {
    extern __shared__ uint2 sm[];

    const int S = S_ROWS, D = DIM;
    const int head = blockIdx.y;
    const int z = blockIdx.z;
    const int s0 = blockIdx.x * 128;
    const int tid = threadIdx.x;
    const int lane = tid & 31;
    const int wid = tid >> 5;
    const int g = lane >> 2;
    const int tig = lane & 3;
    const float scl = 0.17677669529663688f;
    const int TPB = 32 / KVSPLIT;
    const int tbase = z * TPB;

    uint32_t aQH[4][4], aQL[4][4];
    {
        const int ra = s0 + wid * 16 + g;
        const int rb = ra + 8;
        #pragma unroll
        for (int k8 = 0; k8 < 4; k8++) {
            const int c0 = head * 32 + k8 * 8 + tig;
            uint2 p0 = split_tf32(q[(size_t)ra * D + c0] * scl);
            uint2 p1 = split_tf32(q[(size_t)rb * D + c0] * scl);
            uint2 p2 = split_tf32(q[(size_t)ra * D + c0 + 4] * scl);
            uint2 p3 = split_tf32(q[(size_t)rb * D + c0 + 4] * scl);
            aQH[k8][0] = p0.x; aQH[k8][1] = p1.x; aQH[k8][2] = p2.x; aQH[k8][3] = p3.x;
            aQL[k8][0] = p0.y; aQL[k8][1] = p1.y; aQL[k8][2] = p2.y; aQL[k8][3] = p3.y;
        }
    }

    float4 kr[2], vr[2];
    int ldR[2], ldC[2];
    #pragma unroll
    for (int i = 0; i < 2; i++) {
        int cc = i * 256 + tid;
        ldR[i] = cc >> 3;
        ldC[i] = (cc & 7) * 4;
    }

    #pragma unroll
    for (int i = 0; i < 2; i++) {
        size_t off = (size_t)(tbase * 64 + ldR[i]) * D + head * 32 + ldC[i];
        kr[i] = *(const float4*)&k[off];
        vr[i] = *(const float4*)&v[off];
    }
    #pragma unroll
    for (int i = 0; i < 2; i++) {
        FKS(0, ldR[i], ldC[i] + 0) = split_tf32(kr[i].x);
        FKS(0, ldR[i], ldC[i] + 1) = split_tf32(kr[i].y);
        FKS(0, ldR[i], ldC[i] + 2) = split_tf32(kr[i].z);
        FKS(0, ldR[i], ldC[i] + 3) = split_tf32(kr[i].w);
        FVS(0, ldR[i], ldC[i] + 0) = split_tf32(vr[i].x);
        FVS(0, ldR[i], ldC[i] + 1) = split_tf32(vr[i].y);
        FVS(0, ldR[i], ldC[i] + 2) = split_tf32(vr[i].z);
        FVS(0, ldR[i], ldC[i] + 3) = split_tf32(vr[i].w);
    }
    __syncthreads();

    float co[4][4];
    #pragma unroll
    for (int nt = 0; nt < 4; nt++)
        #pragma unroll
        for (int i = 0; i < 4; i++) co[nt][i] = 0.f;
    float m_a = -INFINITY, m_b = -INFINITY, l_a = 0.f, l_b = 0.f;

    for (int j = 0; j < TPB; j++) {
        const int cur = j & 1;
        const int t0 = (tbase + j) * 64;

        if (j + 1 < TPB) {
            const int t1 = t0 + 64;
            #pragma unroll
            for (int i = 0; i < 2; i++) {
                size_t off = (size_t)(t1 + ldR[i]) * D + head * 32 + ldC[i];
                kr[i] = *(const float4*)&k[off];
                vr[i] = *(const float4*)&v[off];
            }
        }

        float cs[8][4];
        #pragma unroll
        for (int nt = 0; nt < 8; nt++)
            #pragma unroll
            for (int i = 0; i < 4; i++) cs[nt][i] = 0.f;

        #pragma unroll
        for (int k8 = 0; k8 < 4; k8++) {
            const int kk = k8 * 8;
            #pragma unroll
            for (int nt = 0; nt < 8; nt++) {
                int ci = nt * 8 + g;
                uint2 q0 = FKS(cur, ci, kk + tig);
                uint2 q1 = FKS(cur, ci, kk + tig + 4);
                uint32_t bH[2] = {q0.x, q1.x};
                uint32_t bL[2] = {q0.y, q1.y};
                mma3(cs[nt], aQH[k8], aQL[k8], bH, bL);
            }
        }

        float mx_a = m_a, mx_b = m_b;
        #pragma unroll
        for (int nt = 0; nt < 8; nt++) {
            int col0 = t0 + nt * 8 + 2 * tig;
            if (col0 >= S)     { cs[nt][0] = -INFINITY; cs[nt][2] = -INFINITY; }
            if (col0 + 1 >= S) { cs[nt][1] = -INFINITY; cs[nt][3] = -INFINITY; }
            mx_a = fmaxf(mx_a, fmaxf(cs[nt][0], cs[nt][1]));
            mx_b = fmaxf(mx_b, fmaxf(cs[nt][2], cs[nt][3]));
        }
        mx_a = fmaxf(mx_a, __shfl_xor_sync(0xffffffffu, mx_a, 1));
        mx_a = fmaxf(mx_a, __shfl_xor_sync(0xffffffffu, mx_a, 2));
        mx_b = fmaxf(mx_b, __shfl_xor_sync(0xffffffffu, mx_b, 1));
        mx_b = fmaxf(mx_b, __shfl_xor_sync(0xffffffffu, mx_b, 2));
        float corr_a = __expf(m_a - mx_a);
        float corr_b = __expf(m_b - mx_b);
        m_a = mx_a; m_b = mx_b;

        float la = 0.f, lb = 0.f;
        #pragma unroll
        for (int nt = 0; nt < 8; nt++) {
            cs[nt][0] = __expf(cs[nt][0] - m_a);
            cs[nt][1] = __expf(cs[nt][1] - m_a);
            cs[nt][2] = __expf(cs[nt][2] - m_b);
            cs[nt][3] = __expf(cs[nt][3] - m_b);
            la += cs[nt][0] + cs[nt][1];
            lb += cs[nt][2] + cs[nt][3];
        }
        la += __shfl_xor_sync(0xffffffffu, la, 1);
        la += __shfl_xor_sync(0xffffffffu, la, 2);
        lb += __shfl_xor_sync(0xffffffffu, lb, 1);
        lb += __shfl_xor_sync(0xffffffffu, lb, 2);
        l_a = l_a * corr_a + la;
        l_b = l_b * corr_b + lb;

        #pragma unroll
        for (int nt = 0; nt < 4; nt++) {
            co[nt][0] *= corr_a; co[nt][1] *= corr_a;
            co[nt][2] *= corr_b; co[nt][3] *= corr_b;
        }

        // PV: permute score C-frags -> A-frags via quad shuffles
        {
            const int s1 = (lane & ~3) | (tig >> 1);
            const int s2 = s1 + 2;
            const bool odd = (tig & 1) != 0;
            #pragma unroll
            for (int k8v = 0; k8v < 8; k8v++) {
                float q00 = __shfl_sync(0xffffffffu, cs[k8v][0], s1);
                float q01 = __shfl_sync(0xffffffffu, cs[k8v][1], s1);
                float q02 = __shfl_sync(0xffffffffu, cs[k8v][2], s1);
                float q03 = __shfl_sync(0xffffffffu, cs[k8v][3], s1);
                float r00 = __shfl_sync(0xffffffffu, cs[k8v][0], s2);
                float r01 = __shfl_sync(0xffffffffu, cs[k8v][1], s2);
                float r02 = __shfl_sync(0xffffffffu, cs[k8v][2], s2);
                float r03 = __shfl_sync(0xffffffffu, cs[k8v][3], s2);
                float a0 = odd ? q01 : q00;
                float a1 = odd ? q03 : q02;
                float a2 = odd ? r01 : r00;
                float a3 = odd ? r03 : r02;
                uint2 h0 = split_tf32(a0), h1 = split_tf32(a1);
                uint2 h2 = split_tf32(a2), h3 = split_tf32(a3);
                uint32_t aH[4] = {h0.x, h1.x, h2.x, h3.x};
                uint32_t aL[4] = {h0.y, h1.y, h2.y, h3.y};
                const int kkv = k8v * 8;
                #pragma unroll
                for (int nt = 0; nt < 4; nt++) {
                    uint2 q0 = FVS(cur, kkv + tig,     nt * 8 + g);
                    uint2 q1 = FVS(cur, kkv + tig + 4, nt * 8 + g);
                    uint32_t bH[2] = {q0.x, q1.x};
                    uint32_t bL[2] = {q0.y, q1.y};
                    mma3(co[nt], aH, aL, bH, bL);
                }
            }
        }

        if (j + 1 < TPB) {
            const int nb = (j + 1) & 1;
            #pragma unroll
            for (int i = 0; i < 2; i++) {
                FKS(nb, ldR[i], ldC[i] + 0) = split_tf32(kr[i].x);
                FKS(nb, ldR[i], ldC[i] + 1) = split_tf32(kr[i].y);
                FKS(nb, ldR[i], ldC[i] + 2) = split_tf32(kr[i].z);
                FKS(nb, ldR[i], ldC[i] + 3) = split_tf32(kr[i].w);
                FVS(nb, ldR[i], ldC[i] + 0) = split_tf32(vr[i].x);
                FVS(nb, ldR[i], ldC[i] + 1) = split_tf32(vr[i].y);
                FVS(nb, ldR[i], ldC[i] + 2) = split_tf32(vr[i].z);
                FVS(nb, ldR[i], ldC[i] + 3) = split_tf32(vr[i].w);
            }
            __syncthreads();
        }
    }

    float* po = g_po[z];
    int srow_a = s0 + wid * 16 + g;
    int srow_b = srow_a + 8;
    #pragma unroll
    for (int nt = 0; nt < 4; nt++) {
        int col = head * 32 + nt * 8 + 2 * tig;
        if (srow_a < S) {
            float2 w2 = make_float2(co[nt][0], co[nt][1]);
            *(float2*)&po[(size_t)srow_a * D + col] = w2;
        }
        if (srow_b < S) {
            float2 w2 = make_float2(co[nt][2], co[nt][3]);
            *(float2*)&po[(size_t)srow_b * D + col] = w2;
        }
    }
    if (tig == 0) {
        if (srow_a < S) g_pml[z][(size_t)srow_a * NHEAD + head] = make_float2(m_a, l_a);
        if (srow_b < S) g_pml[z][(size_t)srow_b * NHEAD + head] = make_float2(m_b, l_b);
    }
}

// ---------------- RQS spline + pos copy + fused deterministic reduction -----
__device__ __forceinline__ float softplusf(float x) {
    return (x > 20.f) ? x : log1pf(expf(x));
}

__global__ void spline_kernel(const float* __restrict__ pos,
                              const float* __restrict__ params,
                              float* __restrict__ out, int out_size) {
    __shared__ float sh[256];
    int t = blockIdx.x * blockDim.x + threadIdx.x;

    float logdet_contrib = 0.f;

    if (t < SPAD) {
        out[t * 3 + 0] = pos[t * 3 + 0];
        out[t * 3 + 1] = pos[t * 3 + 1];
        out[t * 3 + 2] = pos[t * 3 + 2];
    }

    if (t >= 1 && t < SPAD) {
        int s = t - 1;
        const float* p = params + s * AFF_OUT;
        const float MINB = 1e-4f;
        const float MINS = 1e-4f;

        float x = pos[t * 3 + 2];
        bool inside = (x >= 0.f) && (x <= 1.f);
        float xc = fminf(fmaxf(x, 0.f), 1.f);

        float ew[NB], eh[NB];
        float mw = -INFINITY, mh = -INFINITY;
        #pragma unroll
        for (int i = 0; i < NB; i++) { mw = fmaxf(mw, p[i]); mh = fmaxf(mh, p[NB + i]); }
        float sw = 0.f, shh = 0.f;
        #pragma unroll
        for (int i = 0; i < NB; i++) {
            ew[i] = expf(p[i] - mw);        sw += ew[i];
            eh[i] = expf(p[NB + i] - mh);   shh += eh[i];
        }
        float fac = 1.f - NB * MINB;
        float isw = fac / sw, ish = fac / shh;

        float off = logf(expm1f(1.f - MINS));
        float d[NB + 1];
        #pragma unroll
        for (int i = 0; i < NB; i++) d[i] = softplusf(p[2 * NB + i] + off) + MINS;
        d[NB] = d[0];

        float xp[NB + 1], yp[NB + 1];
        xp[0] = 0.f; yp[0] = 0.f;
        #pragma unroll
        for (int i = 0; i < NB; i++) {
            xp[i + 1] = xp[i] + (ew[i] * isw + MINB);
            yp[i + 1] = yp[i] + (eh[i] * ish + MINB);
        }

        int cnt = 0;
        #pragma unroll
        for (int i = 0; i < NB + 1; i++) cnt += (xc >= xp[i]) ? 1 : 0;
        int kb = cnt - 1;
        if (kb < 0) kb = 0;
        if (kb > NB - 1) kb = NB - 1;

        float xk = xp[kb], xk1 = xp[kb + 1];
        float yk = yp[kb], yk1 = yp[kb + 1];
        float dk = d[kb],  dk1 = d[kb + 1];
        float w = xk1 - xk;
        float h = yk1 - yk;
        float sl = h / w;
        float z = (xc - xk) / w;
        float z1 = 1.f - z;
        float den = sl + (dk1 + dk - 2.f * sl) * z * z1;
        float y = yk + h * (sl * z * z + dk * z * z1) / den;
        float logdet = 2.f * logf(sl)
                     + logf(dk1 * z * z + 2.f * sl * z * z1 + dk * z1 * z1)
                     - 2.f * logf(den);

        out[t * 3 + 2] = inside ? y : x;
        logdet_contrib = inside ? logdet : 0.f;
    }

    // ---- block-local deterministic tree reduction ----
    sh[threadIdx.x] = logdet_contrib;
    __syncthreads();
    for (int st = 128; st > 0; st >>= 1) {
        if (threadIdx.x < st) sh[threadIdx.x] += sh[threadIdx.x + st];
        __syncthreads();
    }
    if (threadIdx.x == 0) {
        g_partial[blockIdx.x] = sh[0];
        __threadfence();
        int prev = atomicAdd(&g_arrive, 1);
        if (prev == SPLINE_BLOCKS - 1) {
            // last block: sum partials in fixed index order (deterministic)
            float total = 0.f;
            #pragma unroll
            for (int b = 0; b < SPLINE_BLOCKS; b++) total += g_partial[b];
            if (out_size > POS_ELEMS) out[POS_ELEMS] = total;
            g_arrive = 0;               // reset for next graph replay
        }
    }
}

// ---------------- host orchestration ---------------------------------------
template <typename T>
static void* sym_addr_raw(T& sym) {
    void* p = nullptr;
    cudaGetSymbolAddress(&p, sym);
    return p;
}

static void gemm(const float* A, int lda, const float* W, const float* bias,
                 const float* res, float* C, int Nstore, int Npad,
                 int Kreal, int Kp, bool relu) {
    dim3 grid(Npad / 64, SPAD / 64);
    bool full = (Nstore % 64 == 0) && (Kreal == Kp);
    if (full) {
        if (relu)
            gemm_v9_kernel<true , true ><<<grid, 256, GEMM_SMEM>>>(A, lda, W, bias, res, C, Nstore, Kreal, Kp);
        else
            gemm_v9_kernel<false, true ><<<grid, 256, GEMM_SMEM>>>(A, lda, W, bias, res, C, Nstore, Kreal, Kp);
    } else {
        if (relu)
            gemm_v9_kernel<true , false><<<grid, 256, GEMM_SMEM>>>(A, lda, W, bias, res, C, Nstore, Kreal, Kp);
        else
            gemm_v9_kernel<false, false><<<grid, 256, GEMM_SMEM>>>(A, lda, W, bias, res, C, Nstore, Kreal, Kp);
    }
}

extern "C" void kernel_launch(void* const* d_in, const int* in_sizes, int n_in,
                              void* d_out, int out_size) {
    const float* pos   = (const float*)d_in[0];
    const float* scale = (const float*)d_in[1];
    const float* press = (const float*)d_in[2];
    const float* temp  = (const float*)d_in[3];
    const float* e_w0 = (const float*)d_in[4];
    const float* e_b0 = (const float*)d_in[5];
    const float* e_w1 = (const float*)d_in[6];
    const float* e_b1 = (const float*)d_in[7];
    const float* e_w2 = (const float*)d_in[8];
    const float* e_b2 = (const float*)d_in[9];
    const float* Wq   = (const float*)d_in[10];
    const float* Wk   = (const float*)d_in[11];
    const float* bk   = (const float*)d_in[12];
    const float* Wv   = (const float*)d_in[13];
    const float* Wo   = (const float*)d_in[14];
    const float* bo   = (const float*)d_in[15];
    const float* mw0  = (const float*)d_in[16];
    const float* mb0  = (const float*)d_in[17];
    const float* mw1  = (const float*)d_in[18];
    const float* mb1  = (const float*)d_in[19];
    const float* mw2  = (const float*)d_in[20];
    const float* mb2  = (const float*)d_in[21];
    const float* a_w0 = (const float*)d_in[22];
    const float* a_b0 = (const float*)d_in[23];
    const float* a_w1 = (const float*)d_in[24];
    const float* a_b1 = (const float*)d_in[25];
    const float* a_w2 = (const float*)d_in[26];
    const float* a_b2 = (const float*)d_in[27];

    float* cond   = (float*)sym_addr_raw(g_cond);
    float* bufA   = (float*)sym_addr_raw(g_a);
    float* bufB   = (float*)sym_addr_raw(g_b);
    float* h      = (float*)sym_addr_raw(g_h);
    float* q      = (float*)sym_addr_raw(g_q);
    float* k      = (float*)sym_addr_raw(g_k);
    float* v      = (float*)sym_addr_raw(g_v);
    float* params = (float*)sym_addr_raw(g_params);
    float* out    = (float*)d_out;

    cudaFuncSetAttribute(gemm_v9_kernel<true , true >,
                         cudaFuncAttributeMaxDynamicSharedMemorySize, GEMM_SMEM);
    cudaFuncSetAttribute(gemm_v9_kernel<false, true >,
                         cudaFuncAttributeMaxDynamicSharedMemorySize, GEMM_SMEM);
    cudaFuncSetAttribute(gemm_v9_kernel<true , false>,
                         cudaFuncAttributeMaxDynamicSharedMemorySize, GEMM_SMEM);
    cudaFuncSetAttribute(gemm_v9_kernel<false, false>,
                         cudaFuncAttributeMaxDynamicSharedMemorySize, GEMM_SMEM);
    cudaFuncSetAttribute(gemm_wo_kernel,
                         cudaFuncAttributeMaxDynamicSharedMemorySize, GEMM_SMEM);
    cudaFuncSetAttribute(gemm_qkv_kernel,
                         cudaFuncAttributeMaxDynamicSharedMemorySize, GEMM_SMEM);
    cudaFuncSetAttribute(flash_mma_kernel,
                         cudaFuncAttributeMaxDynamicSharedMemorySize, FLASH_SMEM);

    embed_kernel<<<SPAD / 256, 256>>>(pos, scale, press, temp, cond);

    // embedding MLP: 35 -> 512 -> 512 -> 256
    gemm(cond, CONDP, e_w0, e_b0, nullptr, bufA, HID, HID, EMB_IN, CONDP, true);
    gemm(bufA, HID,   e_w1, e_b1, nullptr, bufB, HID, HID, HID, HID, true);
    gemm(bufB, HID,   e_w2, e_b2, nullptr, h,    DIM, DIM, HID, HID, false);

    for (int i = 0; i < NBLK; i++) {
        const float* Wqi = Wq + (size_t)i * DIM * DIM;
        const float* Wki = Wk + (size_t)i * DIM * DIM;
        const float* bki = bk + (size_t)i * DIM;
        const float* Wvi = Wv + (size_t)i * DIM * DIM;
        const float* Woi = Wo + (size_t)i * DIM * DIM;
        const float* boi = bo + (size_t)i * DIM;
        const float* mw0i = mw0 + (size_t)i * HID * DIM;
        const float* mb0i = mb0 + (size_t)i * HID;
        const float* mw1i = mw1 + (size_t)i * HID * HID;
        const float* mb1i = mb1 + (size_t)i * HID;
        const float* mw2i = mw2 + (size_t)i * DIM * HID;
        const float* mb2i = mb2 + (size_t)i * DIM;

        dim3 qkvgrid(DIM / 64, SPAD / 64, 3);
        gemm_qkv_kernel<<<qkvgrid, 256, GEMM_SMEM>>>(h, Wqi, Wki, Wvi, bki,
                                                     q, k, v);

        dim3 fgrid(SPAD / 128, NHEAD, KVSPLIT);
        flash_mma_kernel<<<fgrid, 256, FLASH_SMEM>>>(q, k, v);

        // h = h + combine(po) @ Wo^T + bo (combine weights cached in smem)
        dim3 wogrid(DIM / 64, SPAD / 64);
        gemm_wo_kernel<<<wogrid, 256, GEMM_SMEM>>>(Woi, boi, h, h);

        gemm(h,    DIM, mw0i, mb0i, nullptr, bufA, HID, HID, DIM, DIM, true);
        gemm(bufA, HID, mw1i, mb1i, nullptr, bufB, HID, HID, HID, HID, true);
        gemm(bufB, HID, mw2i, mb2i, h,       h,    DIM, DIM, HID, HID, false);
    }

    // affine head: 256 -> 512 -> 512 -> 49
    gemm(h,    DIM, a_w0, a_b0, nullptr, bufA,   HID,     HID, DIM, DIM, true);
    gemm(bufA, HID, a_w1, a_b1, nullptr, bufB,   HID,     HID, HID, HID, true);
    gemm(bufB, HID, a_w2, a_b2, nullptr, params, AFF_OUT, 64,  HID, HID, false);

    spline_kernel<<<SPLINE_BLOCKS, 256>>>(pos, params, out, out_size);
}